// round 2
// baseline (speedup 1.0000x reference)
#include <cuda_runtime.h>
#include <cuda_bf16.h>
#include <cstdint>

// ---------------- problem constants ----------------
#define BATCH   2
#define SEQ     2048
#define HIDDEN  2560
#define NHEADS  16
#define NKV     4
#define HDIM    256
#define INNER   (NHEADS * HDIM)          // 4096
#define TOKENS  (BATCH * SEQ)            // 4096
#define GQA     (NHEADS / NKV)           // 4

// ---------------- scratch (static device globals; no runtime alloc) ----------------
__device__ float g_QG[(size_t)TOKENS * 2 * INNER];          // [4096, 8192]  q|gate
__device__ float g_K [(size_t)TOKENS * NKV * HDIM];         // [4096, 1024]
__device__ float g_V [(size_t)TOKENS * NKV * HDIM];         // [4096, 1024]
__device__ float g_Qn[(size_t)BATCH * NHEADS * SEQ * HDIM]; // [B,H,L,D]
__device__ float g_Kn[(size_t)BATCH * NKV    * SEQ * HDIM]; // [B,KV,L,D]
__device__ float g_Vt[(size_t)BATCH * NKV    * SEQ * HDIM]; // [B,KV,L,D]
__device__ float g_Cb[(size_t)TOKENS * INNER];              // gated attn out [4096,4096]

// ---------------- SGEMM: C[M,N] = A[M,K] * B[K,N], all row-major ----------------
// 128x128 block, BK=8, 256 threads, 8x8 per-thread microtile, double-buffered smem.
__global__ __launch_bounds__(256) void sgemm128(
    const float* __restrict__ A, const float* __restrict__ B,
    float* __restrict__ C, int M, int N, int K)
{
    __shared__ float As[2][8][128];
    __shared__ float Bs[2][8][128];

    const int tid = threadIdx.x;
    const int bm = blockIdx.y * 128;
    const int bn = blockIdx.x * 128;
    const int tx = tid & 15;
    const int ty = tid >> 4;

    // A-tile load map: 128 rows x 8 cols; one float4 per thread
    const int arow = tid >> 1;
    const int acol = (tid & 1) * 4;
    // B-tile load map: 8 rows x 128 cols; one float4 per thread (coalesced)
    const int brow = tid >> 5;
    const int bcol = (tid & 31) * 4;

    const float* Ap = A + (size_t)(bm + arow) * K + acol;
    const float* Bp = B + (size_t)brow * N + bn + bcol;

    float acc[8][8];
#pragma unroll
    for (int i = 0; i < 8; i++)
#pragma unroll
        for (int j = 0; j < 8; j++) acc[i][j] = 0.f;

    // prologue: stage k0=0 into buffer 0
    float4 av = *(const float4*)(Ap);
    float4 bv = *(const float4*)(Bp);
    int buf = 0;
    As[0][acol + 0][arow] = av.x;
    As[0][acol + 1][arow] = av.y;
    As[0][acol + 2][arow] = av.z;
    As[0][acol + 3][arow] = av.w;
    *(float4*)&Bs[0][brow][bcol] = bv;
    __syncthreads();

    for (int k0 = 8; k0 < K; k0 += 8) {
        // issue next tile's global loads first (overlap with FMAs below)
        av = *(const float4*)(Ap + k0);
        bv = *(const float4*)(Bp + (size_t)k0 * N);

#pragma unroll
        for (int kk = 0; kk < 8; ++kk) {
            float a[8], b[8];
            *(float4*)&a[0] = *(float4*)&As[buf][kk][ty * 4];
            *(float4*)&a[4] = *(float4*)&As[buf][kk][64 + ty * 4];
            *(float4*)&b[0] = *(float4*)&Bs[buf][kk][tx * 4];
            *(float4*)&b[4] = *(float4*)&Bs[buf][kk][64 + tx * 4];
#pragma unroll
            for (int i = 0; i < 8; i++)
#pragma unroll
                for (int j = 0; j < 8; j++) acc[i][j] += a[i] * b[j];
        }

        const int nb = buf ^ 1;
        As[nb][acol + 0][arow] = av.x;
        As[nb][acol + 1][arow] = av.y;
        As[nb][acol + 2][arow] = av.z;
        As[nb][acol + 3][arow] = av.w;
        *(float4*)&Bs[nb][brow][bcol] = bv;
        __syncthreads();
        buf = nb;
    }

    // epilogue compute on last buffer
#pragma unroll
    for (int kk = 0; kk < 8; ++kk) {
        float a[8], b[8];
        *(float4*)&a[0] = *(float4*)&As[buf][kk][ty * 4];
        *(float4*)&a[4] = *(float4*)&As[buf][kk][64 + ty * 4];
        *(float4*)&b[0] = *(float4*)&Bs[buf][kk][tx * 4];
        *(float4*)&b[4] = *(float4*)&Bs[buf][kk][64 + tx * 4];
#pragma unroll
        for (int i = 0; i < 8; i++)
#pragma unroll
            for (int j = 0; j < 8; j++) acc[i][j] += a[i] * b[j];
    }

#pragma unroll
    for (int i = 0; i < 8; i++) {
        int r = bm + ((i < 4) ? (ty * 4 + i) : (64 + ty * 4 + (i - 4)));
        float* cp = C + (size_t)r * N + bn;
        *(float4*)(cp + tx * 4)      = make_float4(acc[i][0], acc[i][1], acc[i][2], acc[i][3]);
        *(float4*)(cp + 64 + tx * 4) = make_float4(acc[i][4], acc[i][5], acc[i][6], acc[i][7]);
    }
}

// ---------------- RMSNorm + RoPE + transpose (one warp per (token, head)) ----------------
// warps [0, 65536): Q heads  -> g_Qn (attn scale 1/16 folded in)
// warps [65536, 81920): K heads -> g_Kn
// warps [81920, 98304): V heads -> g_Vt (transpose only)
__global__ __launch_bounds__(256) void norm_rope_kernel(
    const float* __restrict__ cosT, const float* __restrict__ sinT,
    const float* __restrict__ qw, const float* __restrict__ kw)
{
    const int gw   = (blockIdx.x * blockDim.x + threadIdx.x) >> 5;
    const int lane = threadIdx.x & 31;
    const int d0 = lane * 4;        // dims d0..d0+3 and 128+d0..128+d0+3
    const int NQ = TOKENS * NHEADS;
    const int NK = TOKENS * NKV;

    if (gw < NQ + NK) {
        const bool isq = (gw < NQ);
        const int p  = isq ? gw : gw - NQ;
        const int nh = isq ? NHEADS : NKV;
        const int t  = p / nh;
        const int h  = p % nh;
        const int b  = t >> 11;          // / SEQ
        const int l  = t & 2047;

        const float* src = (isq ? g_QG : g_K) +
                           (size_t)t * (isq ? 2 * INNER : NKV * HDIM) + h * HDIM;
        float x[8];
        *(float4*)&x[0] = *(const float4*)(src + d0);
        *(float4*)&x[4] = *(const float4*)(src + 128 + d0);

        float ss = 0.f;
#pragma unroll
        for (int i = 0; i < 8; i++) ss += x[i] * x[i];
#pragma unroll
        for (int off = 16; off > 0; off >>= 1) ss += __shfl_xor_sync(0xffffffffu, ss, off);

        float rs = rsqrtf(ss * (1.0f / 256.0f) + 1e-6f);
        if (isq) rs *= 0.0625f;          // fold 1/sqrt(256) attention scale into Q

        const float* w = isq ? qw : kw;
        float wv[8];
        *(float4*)&wv[0] = *(const float4*)(w + d0);
        *(float4*)&wv[4] = *(const float4*)(w + 128 + d0);

        float cs[8], sn[8];
        const float* cp = cosT + (size_t)l * HDIM;
        const float* sp = sinT + (size_t)l * HDIM;
        *(float4*)&cs[0] = *(const float4*)(cp + d0);
        *(float4*)&cs[4] = *(const float4*)(cp + 128 + d0);
        *(float4*)&sn[0] = *(const float4*)(sp + d0);
        *(float4*)&sn[4] = *(const float4*)(sp + 128 + d0);

        float n[8], o[8];
#pragma unroll
        for (int i = 0; i < 8; i++) n[i] = x[i] * rs * wv[i];
#pragma unroll
        for (int j = 0; j < 4; j++) {
            o[j]     = n[j]     * cs[j]     - n[4 + j] * sn[j];
            o[4 + j] = n[4 + j] * cs[4 + j] + n[j]     * sn[4 + j];
        }

        float* dst = (isq ? g_Qn : g_Kn) +
                     ((size_t)(b * nh + h) * SEQ + l) * HDIM;
        *(float4*)(dst + d0)       = *(float4*)&o[0];
        *(float4*)(dst + 128 + d0) = *(float4*)&o[4];
    } else {
        // V transpose path
        const int p  = gw - NQ - NK;
        const int t  = p / NKV;
        const int kv = p % NKV;
        const int b  = t >> 11;
        const int l  = t & 2047;
        const float* src = g_V + (size_t)t * (NKV * HDIM) + kv * HDIM;
        float* dst = g_Vt + ((size_t)(b * NKV + kv) * SEQ + l) * HDIM;
        *(float4*)(dst + d0)       = *(const float4*)(src + d0);
        *(float4*)(dst + 128 + d0) = *(const float4*)(src + 128 + d0);
    }
}

// ---------------- causal flash attention + SiLU gate epilogue ----------------
// grid = (SEQ/8, B*NHEADS); block = 256 (8 warps, 1 query each).
// Shared: K tile [32][256] + V tile [32][256] = 64 KB dynamic.
__global__ __launch_bounds__(256) void attn_kernel()
{
    extern __shared__ float smem[];
    float (*Ksh)[HDIM] = (float (*)[HDIM])smem;
    float (*Vsh)[HDIM] = (float (*)[HDIM])(smem + 32 * HDIM);

    const int tid  = threadIdx.x;
    const int lane = tid & 31;
    const int wrp  = tid >> 5;
    const int bh = blockIdx.y;
    const int b  = bh >> 4;          // / NHEADS
    const int h  = bh & 15;
    const int kv = h / GQA;
    const int q0 = blockIdx.x * 8;
    const int q  = q0 + wrp;

    const int d0 = lane * 4;

    // load my query row (scale already folded in)
    const float* qp = g_Qn + ((size_t)(b * NHEADS + h) * SEQ + q) * HDIM;
    float qr[8];
    *(float4*)&qr[0] = *(const float4*)(qp + d0);
    *(float4*)&qr[4] = *(const float4*)(qp + 128 + d0);

    float m = -1e30f, lsum = 0.f;
    float o[8];
#pragma unroll
    for (int i = 0; i < 8; i++) o[i] = 0.f;

    const float* kbase = g_Kn + (size_t)(b * NKV + kv) * SEQ * HDIM;
    const float* vbase = g_Vt + (size_t)(b * NKV + kv) * SEQ * HDIM;

    const int ntiles = (q0 + 8 + 31) / 32;
    for (int kt = 0; kt < ntiles; ++kt) {
        __syncthreads();
        // cooperative tile load: 2048 float4 / 256 threads = 8 each
        const float* kp = kbase + (size_t)kt * 32 * HDIM;
        const float* vp = vbase + (size_t)kt * 32 * HDIM;
#pragma unroll
        for (int i = 0; i < 8; i++) {
            int idx4 = tid + i * 256;
            int row  = idx4 >> 6;
            int c    = (idx4 & 63) * 4;
            *(float4*)&Ksh[row][c] = *(const float4*)(kp + row * HDIM + c);
            *(float4*)&Vsh[row][c] = *(const float4*)(vp + row * HDIM + c);
        }
        __syncthreads();

        const int jmax = min(31, q - kt * 32);
        for (int j = 0; j <= jmax; ++j) {
            float kr[8], vr[8];
            *(float4*)&kr[0] = *(float4*)&Ksh[j][d0];
            *(float4*)&kr[4] = *(float4*)&Ksh[j][128 + d0];
            float s = 0.f;
#pragma unroll
            for (int i = 0; i < 8; i++) s += qr[i] * kr[i];
#pragma unroll
            for (int off = 16; off > 0; off >>= 1) s += __shfl_xor_sync(0xffffffffu, s, off);

            float mn = fmaxf(m, s);
            float c  = __expf(m - mn);
            float p  = __expf(s - mn);
            lsum = lsum * c + p;
            *(float4*)&vr[0] = *(float4*)&Vsh[j][d0];
            *(float4*)&vr[4] = *(float4*)&Vsh[j][128 + d0];
#pragma unroll
            for (int i = 0; i < 8; i++) o[i] = o[i] * c + p * vr[i];
            m = mn;
        }
    }

    // epilogue: normalize + SiLU(gate)
    const float inv = 1.0f / lsum;
    const int t = b * SEQ + q;
    const float* gp = g_QG + (size_t)t * (2 * INNER) + INNER + h * HDIM;
    float gv[8];
    *(float4*)&gv[0] = *(const float4*)(gp + d0);
    *(float4*)&gv[4] = *(const float4*)(gp + 128 + d0);
    float r[8];
#pragma unroll
    for (int i = 0; i < 8; i++) {
        float g   = gv[i];
        float sil = g / (1.0f + __expf(-g));
        r[i] = o[i] * inv * sil;
    }
    float* dst = g_Cb + (size_t)t * INNER + h * HDIM;
    *(float4*)(dst + d0)       = *(float4*)&r[0];
    *(float4*)(dst + 128 + d0) = *(float4*)&r[4];
}

// ---------------- host launcher ----------------
extern "C" void kernel_launch(void* const* d_in, const int* in_sizes, int n_in,
                              void* d_out, int out_size)
{
    const float* hidden = (const float*)d_in[0];
    const float* cosT   = (const float*)d_in[1];
    const float* sinT   = (const float*)d_in[2];
    const float* Wq     = (const float*)d_in[3];
    const float* Wk     = (const float*)d_in[4];
    const float* Wv     = (const float*)d_in[5];
    const float* Wo     = (const float*)d_in[6];
    const float* qw     = (const float*)d_in[7];
    const float* kw     = (const float*)d_in[8];
    float* out = (float*)d_out;

    float *QG, *K, *V, *Cb;
    cudaGetSymbolAddress((void**)&QG, g_QG);
    cudaGetSymbolAddress((void**)&K,  g_K);
    cudaGetSymbolAddress((void**)&V,  g_V);
    cudaGetSymbolAddress((void**)&Cb, g_Cb);

    // 1) projections
    sgemm128<<<dim3(2 * INNER / 128, TOKENS / 128), 256>>>(hidden, Wq, QG, TOKENS, 2 * INNER, HIDDEN);
    sgemm128<<<dim3(NKV * HDIM / 128, TOKENS / 128), 256>>>(hidden, Wk, K, TOKENS, NKV * HDIM, HIDDEN);
    sgemm128<<<dim3(NKV * HDIM / 128, TOKENS / 128), 256>>>(hidden, Wv, V, TOKENS, NKV * HDIM, HIDDEN);

    // 2) RMSNorm + RoPE + transpose
    const int total_warps = TOKENS * (NHEADS + NKV + NKV);
    norm_rope_kernel<<<total_warps / 8, 256>>>(cosT, sinT, qw, kw);

    // 3) causal attention + gate
    static_assert(32 * HDIM * 2 * sizeof(float) == 65536, "smem size");
    cudaFuncSetAttribute(attn_kernel, cudaFuncAttributeMaxDynamicSharedMemorySize, 65536);
    attn_kernel<<<dim3(SEQ / 8, BATCH * NHEADS), 256, 65536>>>();

    // 4) output projection -> d_out
    sgemm128<<<dim3(HIDDEN / 128, TOKENS / 128), 256>>>(Cb, Wo, out, TOKENS, HIDDEN, INNER);
}

// round 5
// speedup vs baseline: 1.4084x; 1.4084x over previous
#include <cuda_runtime.h>
#include <cuda_bf16.h>
#include <cstdint>

// ---------------- problem constants ----------------
#define BATCH   2
#define SEQ     2048
#define HIDDEN  2560
#define NHEADS  16
#define NKV     4
#define HDIM    256
#define INNER   (NHEADS * HDIM)          // 4096
#define TOKENS  (BATCH * SEQ)            // 4096
#define GQA     (NHEADS / NKV)           // 4

// ---------------- scratch (static device globals; no runtime alloc) ----------------
__device__ float g_QG[(size_t)TOKENS * 2 * INNER];          // [4096, 8192]  q|gate
__device__ float g_K [(size_t)TOKENS * NKV * HDIM];         // [4096, 1024]
__device__ float g_V [(size_t)TOKENS * NKV * HDIM];         // [4096, 1024]
__device__ float g_Qn[(size_t)BATCH * NHEADS * SEQ * HDIM]; // [B,H,L,D]
__device__ float g_Kn[(size_t)BATCH * NKV    * SEQ * HDIM]; // [B,KV,L,D]
__device__ float g_Vt[(size_t)BATCH * NKV    * SEQ * HDIM]; // [B,KV,L,D]
__device__ float g_Cb[(size_t)TOKENS * INNER];              // gated attn out [4096,4096]

// bf16 split operands
__device__ __nv_bfloat16 g_Xhi [(size_t)TOKENS * HIDDEN];
__device__ __nv_bfloat16 g_Xlo [(size_t)TOKENS * HIDDEN];
__device__ __nv_bfloat16 g_WqTh[(size_t)2 * INNER * HIDDEN];   // [8192, 2560]
__device__ __nv_bfloat16 g_WqTl[(size_t)2 * INNER * HIDDEN];
__device__ __nv_bfloat16 g_WkTh[(size_t)NKV * HDIM * HIDDEN];  // [1024, 2560]
__device__ __nv_bfloat16 g_WkTl[(size_t)NKV * HDIM * HIDDEN];
__device__ __nv_bfloat16 g_WvTh[(size_t)NKV * HDIM * HIDDEN];
__device__ __nv_bfloat16 g_WvTl[(size_t)NKV * HDIM * HIDDEN];
__device__ __nv_bfloat16 g_WoTh[(size_t)HIDDEN * INNER];       // [2560, 4096]
__device__ __nv_bfloat16 g_WoTl[(size_t)HIDDEN * INNER];
__device__ __nv_bfloat16 g_Cbh [(size_t)TOKENS * INNER];
__device__ __nv_bfloat16 g_Cbl [(size_t)TOKENS * INNER];

// ---------------- helpers ----------------
__device__ __forceinline__ uint32_t smem_to_u32(const void* p) {
    uint32_t a;
    asm("{ .reg .u64 t; cvta.to.shared.u64 t, %1; cvt.u32.u64 %0, t; }" : "=r"(a) : "l"(p));
    return a;
}
#define SWZ128(o)  ((o) ^ (((o) >> 3) & 0x70))

__device__ __forceinline__ void cp16(uint32_t dst, const void* src) {
    asm volatile("cp.async.cg.shared.global [%0], [%1], 16;" :: "r"(dst), "l"(src));
}
#define CP_COMMIT()  asm volatile("cp.async.commit_group;" ::: "memory")
#define CP_WAIT(n)   asm volatile("cp.async.wait_group %0;" :: "n"(n) : "memory")

__device__ __forceinline__ void ldm_x4(uint32_t* r, uint32_t addr) {
    asm volatile("ldmatrix.sync.aligned.m8n8.x4.shared.b16 {%0,%1,%2,%3}, [%4];"
                 : "=r"(r[0]), "=r"(r[1]), "=r"(r[2]), "=r"(r[3]) : "r"(addr));
}
__device__ __forceinline__ void ldm_x2(uint32_t* r, uint32_t addr) {
    asm volatile("ldmatrix.sync.aligned.m8n8.x2.shared.b16 {%0,%1}, [%2];"
                 : "=r"(r[0]), "=r"(r[1]) : "r"(addr));
}
__device__ __forceinline__ void mma16816(float* d, const uint32_t* a, const uint32_t* b) {
    asm volatile("mma.sync.aligned.m16n8k16.row.col.f32.bf16.bf16.f32 "
                 "{%0,%1,%2,%3}, {%4,%5,%6,%7}, {%8,%9}, {%0,%1,%2,%3};"
                 : "+f"(d[0]), "+f"(d[1]), "+f"(d[2]), "+f"(d[3])
                 : "r"(a[0]), "r"(a[1]), "r"(a[2]), "r"(a[3]), "r"(b[0]), "r"(b[1]));
}

// ---------------- split-precision convert: fp32 -> bf16 hi/lo ----------------
__global__ __launch_bounds__(256) void split_kernel(
    const float4* __restrict__ X, __nv_bfloat162* __restrict__ Hi,
    __nv_bfloat162* __restrict__ Lo, int n4)
{
    int i = blockIdx.x * 256 + threadIdx.x;
    if (i >= n4) return;
    float4 x = X[i];
    __nv_bfloat16 h0 = __float2bfloat16(x.x), h1 = __float2bfloat16(x.y);
    __nv_bfloat16 h2 = __float2bfloat16(x.z), h3 = __float2bfloat16(x.w);
    __nv_bfloat16 l0 = __float2bfloat16(x.x - __bfloat162float(h0));
    __nv_bfloat16 l1 = __float2bfloat16(x.y - __bfloat162float(h1));
    __nv_bfloat16 l2 = __float2bfloat16(x.z - __bfloat162float(h2));
    __nv_bfloat16 l3 = __float2bfloat16(x.w - __bfloat162float(h3));
    __nv_bfloat162 p;
    p.x = h0; p.y = h1; Hi[2 * i]     = p;
    p.x = h2; p.y = h3; Hi[2 * i + 1] = p;
    p.x = l0; p.y = l1; Lo[2 * i]     = p;
    p.x = l2; p.y = l3; Lo[2 * i + 1] = p;
}

// ---------------- transpose + split: W[K,N] fp32 -> T[N,K] bf16 hi/lo ----------------
__global__ __launch_bounds__(256) void transpose_split_kernel(
    const float* __restrict__ W, __nv_bfloat16* __restrict__ Thi,
    __nv_bfloat16* __restrict__ Tlo, int K, int N)
{
    __shared__ float s[32][33];
    const int tx = threadIdx.x, ty = threadIdx.y;
    const int n0 = blockIdx.x * 32, k0 = blockIdx.y * 32;
#pragma unroll
    for (int i = 0; i < 4; i++)
        s[ty + i * 8][tx] = W[(size_t)(k0 + ty + i * 8) * N + n0 + tx];
    __syncthreads();
#pragma unroll
    for (int i = 0; i < 4; i++) {
        float v = s[tx][ty + i * 8];
        __nv_bfloat16 h = __float2bfloat16(v);
        __nv_bfloat16 l = __float2bfloat16(v - __bfloat162float(h));
        size_t o = (size_t)(n0 + ty + i * 8) * K + k0 + tx;
        Thi[o] = h; Tlo[o] = l;
    }
}

// ---------------- HMMA bf16-split GEMM (mma.sync m16n8k16) ----------------
// C[M,N] = (Ahi+Alo)[M,K] @ (Bhi+Blo)[N,K]^T, fp32 accumulate.
// 128x128 CTA tile, BK=64, 8 warps (2x4), 2-stage cp.async pipeline.
#define BM 128
#define BN 128
#define BKG 64
#define TILE_B 16384                 // 128 rows x 128 bytes
#define STAGE_B (4 * TILE_B)         // Ah, Al, Bh, Bl
#define GSMEM (2 * STAGE_B)          // 128 KB

__global__ __launch_bounds__(256) void gemm_bf16split(
    const __nv_bfloat16* __restrict__ Ahi, const __nv_bfloat16* __restrict__ Alo,
    const __nv_bfloat16* __restrict__ Bhi, const __nv_bfloat16* __restrict__ Blo,
    float* __restrict__ C, int M, int N, int K)
{
    extern __shared__ char dynsmem[];
    const uint32_t sb = smem_to_u32(dynsmem);
    const int tid = threadIdx.x;
    const int lane = tid & 31;
    const int wid = tid >> 5;
    const int wm = wid >> 2;          // 0..1
    const int wn = wid & 3;           // 0..3

    const int bm = blockIdx.y * BM;
    const int bn = blockIdx.x * BN;
    const __nv_bfloat16* A0 = Ahi + (size_t)bm * K;
    const __nv_bfloat16* A1 = Alo + (size_t)bm * K;
    const __nv_bfloat16* B0 = Bhi + (size_t)bn * K;
    const __nv_bfloat16* B1 = Blo + (size_t)bn * K;

    float acc[4][4][4];
#pragma unroll
    for (int i = 0; i < 4; i++)
#pragma unroll
        for (int j = 0; j < 4; j++)
#pragma unroll
            for (int r = 0; r < 4; r++) acc[i][j][r] = 0.f;

    const int NC = K / BKG;

    // per-thread load coords: 1024 16B-chunks per tile, 4 per thread per tile
    const int lr0 = tid >> 1;              // rows tid/2 and tid/2+... (4 rows per thread? no:)
    // simpler: idx = tid + i*256, row = idx>>3, c16 = idx&7
#define LOAD_STAGE(sg, ch) do { \
        uint32_t base = sb + (sg) * STAGE_B; \
        size_t kc = (size_t)(ch) * BKG; \
        _Pragma("unroll") \
        for (int i = 0; i < 4; i++) { \
            int idx = tid + i * 256; \
            int row = idx >> 3, c16 = idx & 7; \
            uint32_t so = SWZ128((uint32_t)(row * 128 + c16 * 16)); \
            size_t go = (size_t)row * K + kc + c16 * 8; \
            cp16(base + 0 * TILE_B + so, A0 + go); \
            cp16(base + 1 * TILE_B + so, A1 + go); \
            cp16(base + 2 * TILE_B + so, B0 + go); \
            cp16(base + 3 * TILE_B + so, B1 + go); \
        } } while (0)

    LOAD_STAGE(0, 0);
    CP_COMMIT();

    const int a_r = (lane & 15);
    const int a_c16 = (lane >> 4) * 16;
    const int b_r = (lane & 7);
    const int b_c16 = ((lane >> 3) & 1) * 16;

    for (int ch = 0; ch < NC; ++ch) {
        const int sg = ch & 1;
        if (ch + 1 < NC) {
            LOAD_STAGE(sg ^ 1, ch + 1);
            CP_COMMIT();
            CP_WAIT(1);
        } else {
            CP_WAIT(0);
        }
        __syncthreads();

        const uint32_t bah = sb + sg * STAGE_B;
        const uint32_t bal = bah + TILE_B;
        const uint32_t bbh = bah + 2 * TILE_B;
        const uint32_t bbl = bah + 3 * TILE_B;

#pragma unroll
        for (int ks = 0; ks < 4; ++ks) {
            uint32_t ah[4][4], al[4][4], bh[4][2], bl[4][2];
#pragma unroll
            for (int i = 0; i < 4; i++) {
                uint32_t off = SWZ128((uint32_t)((wm * 64 + i * 16 + a_r) * 128 + ks * 32 + a_c16));
                ldm_x4(ah[i], bah + off);
                ldm_x4(al[i], bal + off);
            }
#pragma unroll
            for (int j = 0; j < 4; j++) {
                uint32_t off = SWZ128((uint32_t)((wn * 32 + j * 8 + b_r) * 128 + ks * 32 + b_c16));
                ldm_x2(bh[j], bbh + off);
                ldm_x2(bl[j], bbl + off);
            }
#pragma unroll
            for (int i = 0; i < 4; i++)
#pragma unroll
                for (int j = 0; j < 4; j++) {
                    mma16816(acc[i][j], ah[i], bh[j]);
                    mma16816(acc[i][j], ah[i], bl[j]);
                    mma16816(acc[i][j], al[i], bh[j]);
                }
        }
        __syncthreads();
    }

    // epilogue: fragment layout m16n8 -> rows (lane>>2, +8), cols (lane&3)*2
    const int r0 = bm + wm * 64 + (lane >> 2);
    const int c0 = bn + wn * 32 + (lane & 3) * 2;
#pragma unroll
    for (int i = 0; i < 4; i++)
#pragma unroll
        for (int j = 0; j < 4; j++) {
            float* p0 = C + (size_t)(r0 + i * 16) * N + c0 + j * 8;
            float* p1 = C + (size_t)(r0 + i * 16 + 8) * N + c0 + j * 8;
            *(float2*)p0 = make_float2(acc[i][j][0], acc[i][j][1]);
            *(float2*)p1 = make_float2(acc[i][j][2], acc[i][j][3]);
        }
}

// ---------------- RMSNorm + RoPE + transpose (one warp per (token, head)) ----------------
__global__ __launch_bounds__(256) void norm_rope_kernel(
    const float* __restrict__ cosT, const float* __restrict__ sinT,
    const float* __restrict__ qw, const float* __restrict__ kw)
{
    const int gw   = (blockIdx.x * blockDim.x + threadIdx.x) >> 5;
    const int lane = threadIdx.x & 31;
    const int d0 = lane * 4;
    const int NQ = TOKENS * NHEADS;
    const int NK = TOKENS * NKV;

    if (gw < NQ + NK) {
        const bool isq = (gw < NQ);
        const int p  = isq ? gw : gw - NQ;
        const int nh = isq ? NHEADS : NKV;
        const int t  = p / nh;
        const int h  = p % nh;
        const int b  = t >> 11;
        const int l  = t & 2047;

        const float* src = (isq ? g_QG : g_K) +
                           (size_t)t * (isq ? 2 * INNER : NKV * HDIM) + h * HDIM;
        float x[8];
        *(float4*)&x[0] = *(const float4*)(src + d0);
        *(float4*)&x[4] = *(const float4*)(src + 128 + d0);

        float ss = 0.f;
#pragma unroll
        for (int i = 0; i < 8; i++) ss += x[i] * x[i];
#pragma unroll
        for (int off = 16; off > 0; off >>= 1) ss += __shfl_xor_sync(0xffffffffu, ss, off);

        float rs = rsqrtf(ss * (1.0f / 256.0f) + 1e-6f);
        if (isq) rs *= 0.0625f;

        const float* w = isq ? qw : kw;
        float wv[8];
        *(float4*)&wv[0] = *(const float4*)(w + d0);
        *(float4*)&wv[4] = *(const float4*)(w + 128 + d0);

        float cs[8], sn[8];
        const float* cp = cosT + (size_t)l * HDIM;
        const float* sp = sinT + (size_t)l * HDIM;
        *(float4*)&cs[0] = *(const float4*)(cp + d0);
        *(float4*)&cs[4] = *(const float4*)(cp + 128 + d0);
        *(float4*)&sn[0] = *(const float4*)(sp + d0);
        *(float4*)&sn[4] = *(const float4*)(sp + 128 + d0);

        float n[8], o[8];
#pragma unroll
        for (int i = 0; i < 8; i++) n[i] = x[i] * rs * wv[i];
#pragma unroll
        for (int j = 0; j < 4; j++) {
            o[j]     = n[j]     * cs[j]     - n[4 + j] * sn[j];
            o[4 + j] = n[4 + j] * cs[4 + j] + n[j]     * sn[4 + j];
        }

        float* dst = (isq ? g_Qn : g_Kn) +
                     ((size_t)(b * nh + h) * SEQ + l) * HDIM;
        *(float4*)(dst + d0)       = *(float4*)&o[0];
        *(float4*)(dst + 128 + d0) = *(float4*)&o[4];
    } else {
        const int p  = gw - NQ - NK;
        const int t  = p / NKV;
        const int kv = p % NKV;
        const int b  = t >> 11;
        const int l  = t & 2047;
        const float* src = g_V + (size_t)t * (NKV * HDIM) + kv * HDIM;
        float* dst = g_Vt + ((size_t)(b * NKV + kv) * SEQ + l) * HDIM;
        *(float4*)(dst + d0)       = *(const float4*)(src + d0);
        *(float4*)(dst + 128 + d0) = *(const float4*)(src + 128 + d0);
    }
}

// ---------------- causal flash attention + SiLU gate epilogue ----------------
__global__ __launch_bounds__(256) void attn_kernel()
{
    extern __shared__ char dynsmem[];
    float* smem = (float*)dynsmem;
    float (*Ksh)[HDIM] = (float (*)[HDIM])smem;
    float (*Vsh)[HDIM] = (float (*)[HDIM])(smem + 32 * HDIM);

    const int tid  = threadIdx.x;
    const int lane = tid & 31;
    const int wrp  = tid >> 5;
    const int bh = blockIdx.y;
    const int b  = bh >> 4;
    const int h  = bh & 15;
    const int kv = h / GQA;
    const int q0 = blockIdx.x * 8;
    const int q  = q0 + wrp;

    const int d0 = lane * 4;

    const float* qp = g_Qn + ((size_t)(b * NHEADS + h) * SEQ + q) * HDIM;
    float qr[8];
    *(float4*)&qr[0] = *(const float4*)(qp + d0);
    *(float4*)&qr[4] = *(const float4*)(qp + 128 + d0);

    float m = -1e30f, lsum = 0.f;
    float o[8];
#pragma unroll
    for (int i = 0; i < 8; i++) o[i] = 0.f;

    const float* kbase = g_Kn + (size_t)(b * NKV + kv) * SEQ * HDIM;
    const float* vbase = g_Vt + (size_t)(b * NKV + kv) * SEQ * HDIM;

    const int ntiles = (q0 + 8 + 31) / 32;
    for (int kt = 0; kt < ntiles; ++kt) {
        __syncthreads();
        const float* kp = kbase + (size_t)kt * 32 * HDIM;
        const float* vp = vbase + (size_t)kt * 32 * HDIM;
#pragma unroll
        for (int i = 0; i < 8; i++) {
            int idx4 = tid + i * 256;
            int row  = idx4 >> 6;
            int c    = (idx4 & 63) * 4;
            *(float4*)&Ksh[row][c] = *(const float4*)(kp + row * HDIM + c);
            *(float4*)&Vsh[row][c] = *(const float4*)(vp + row * HDIM + c);
        }
        __syncthreads();

        const int jmax = min(31, q - kt * 32);
        for (int j = 0; j <= jmax; ++j) {
            float kr[8], vr[8];
            *(float4*)&kr[0] = *(float4*)&Ksh[j][d0];
            *(float4*)&kr[4] = *(float4*)&Ksh[j][128 + d0];
            float s = 0.f;
#pragma unroll
            for (int i = 0; i < 8; i++) s += qr[i] * kr[i];
#pragma unroll
            for (int off = 16; off > 0; off >>= 1) s += __shfl_xor_sync(0xffffffffu, s, off);

            float mn = fmaxf(m, s);
            float c  = __expf(m - mn);
            float p  = __expf(s - mn);
            lsum = lsum * c + p;
            *(float4*)&vr[0] = *(float4*)&Vsh[j][d0];
            *(float4*)&vr[4] = *(float4*)&Vsh[j][128 + d0];
#pragma unroll
            for (int i = 0; i < 8; i++) o[i] = o[i] * c + p * vr[i];
            m = mn;
        }
    }

    const float inv = 1.0f / lsum;
    const int t = b * SEQ + q;
    const float* gp = g_QG + (size_t)t * (2 * INNER) + INNER + h * HDIM;
    float gv[8];
    *(float4*)&gv[0] = *(const float4*)(gp + d0);
    *(float4*)&gv[4] = *(const float4*)(gp + 128 + d0);
    float r[8];
#pragma unroll
    for (int i = 0; i < 8; i++) {
        float g   = gv[i];
        float sil = g / (1.0f + __expf(-g));
        r[i] = o[i] * inv * sil;
    }
    float* dst = g_Cb + (size_t)t * INNER + h * HDIM;
    *(float4*)(dst + d0)       = *(float4*)&r[0];
    *(float4*)(dst + 128 + d0) = *(float4*)&r[4];
}

// ---------------- host launcher ----------------
extern "C" void kernel_launch(void* const* d_in, const int* in_sizes, int n_in,
                              void* d_out, int out_size)
{
    const float* hidden = (const float*)d_in[0];
    const float* cosT   = (const float*)d_in[1];
    const float* sinT   = (const float*)d_in[2];
    const float* Wq     = (const float*)d_in[3];
    const float* Wk     = (const float*)d_in[4];
    const float* Wv     = (const float*)d_in[5];
    const float* Wo     = (const float*)d_in[6];
    const float* qw     = (const float*)d_in[7];
    const float* kw     = (const float*)d_in[8];
    float* out = (float*)d_out;

    float *QG, *K, *V, *Cb;
    __nv_bfloat16 *Xhi, *Xlo, *WqTh, *WqTl, *WkTh, *WkTl, *WvTh, *WvTl, *WoTh, *WoTl, *Cbh, *Cbl;
    cudaGetSymbolAddress((void**)&QG, g_QG);
    cudaGetSymbolAddress((void**)&K,  g_K);
    cudaGetSymbolAddress((void**)&V,  g_V);
    cudaGetSymbolAddress((void**)&Cb, g_Cb);
    cudaGetSymbolAddress((void**)&Xhi,  g_Xhi);
    cudaGetSymbolAddress((void**)&Xlo,  g_Xlo);
    cudaGetSymbolAddress((void**)&WqTh, g_WqTh);
    cudaGetSymbolAddress((void**)&WqTl, g_WqTl);
    cudaGetSymbolAddress((void**)&WkTh, g_WkTh);
    cudaGetSymbolAddress((void**)&WkTl, g_WkTl);
    cudaGetSymbolAddress((void**)&WvTh, g_WvTh);
    cudaGetSymbolAddress((void**)&WvTl, g_WvTl);
    cudaGetSymbolAddress((void**)&WoTh, g_WoTh);
    cudaGetSymbolAddress((void**)&WoTl, g_WoTl);
    cudaGetSymbolAddress((void**)&Cbh,  g_Cbh);
    cudaGetSymbolAddress((void**)&Cbl,  g_Cbl);

    // 0) split/transpose operands to bf16 hi/lo
    {
        int n4 = TOKENS * HIDDEN / 4;
        split_kernel<<<(n4 + 255) / 256, 256>>>((const float4*)hidden,
            (__nv_bfloat162*)Xhi, (__nv_bfloat162*)Xlo, n4);
    }
    transpose_split_kernel<<<dim3(2 * INNER / 32, HIDDEN / 32), dim3(32, 8)>>>(Wq, WqTh, WqTl, HIDDEN, 2 * INNER);
    transpose_split_kernel<<<dim3(NKV * HDIM / 32, HIDDEN / 32), dim3(32, 8)>>>(Wk, WkTh, WkTl, HIDDEN, NKV * HDIM);
    transpose_split_kernel<<<dim3(NKV * HDIM / 32, HIDDEN / 32), dim3(32, 8)>>>(Wv, WvTh, WvTl, HIDDEN, NKV * HDIM);
    transpose_split_kernel<<<dim3(HIDDEN / 32, INNER / 32), dim3(32, 8)>>>(Wo, WoTh, WoTl, INNER, HIDDEN);

    // 1) projections (HMMA bf16-split)
    cudaFuncSetAttribute(gemm_bf16split, cudaFuncAttributeMaxDynamicSharedMemorySize, GSMEM);
    gemm_bf16split<<<dim3(2 * INNER / BN, TOKENS / BM), 256, GSMEM>>>(
        Xhi, Xlo, WqTh, WqTl, QG, TOKENS, 2 * INNER, HIDDEN);
    gemm_bf16split<<<dim3(NKV * HDIM / BN, TOKENS / BM), 256, GSMEM>>>(
        Xhi, Xlo, WkTh, WkTl, K, TOKENS, NKV * HDIM, HIDDEN);
    gemm_bf16split<<<dim3(NKV * HDIM / BN, TOKENS / BM), 256, GSMEM>>>(
        Xhi, Xlo, WvTh, WvTl, V, TOKENS, NKV * HDIM, HIDDEN);

    // 2) RMSNorm + RoPE + transpose
    const int total_warps = TOKENS * (NHEADS + NKV + NKV);
    norm_rope_kernel<<<total_warps / 8, 256>>>(cosT, sinT, qw, kw);

    // 3) causal attention + gate
    cudaFuncSetAttribute(attn_kernel, cudaFuncAttributeMaxDynamicSharedMemorySize, 65536);
    attn_kernel<<<dim3(SEQ / 8, BATCH * NHEADS), 256, 65536>>>();

    // 4) output projection -> d_out (split Cb then HMMA GEMM)
    {
        int n4 = TOKENS * INNER / 4;
        split_kernel<<<(n4 + 255) / 256, 256>>>((const float4*)Cb,
            (__nv_bfloat162*)Cbh, (__nv_bfloat162*)Cbl, n4);
    }
    gemm_bf16split<<<dim3(HIDDEN / BN, TOKENS / BM), 256, GSMEM>>>(
        Cbh, Cbl, WoTh, WoTl, out, TOKENS, HIDDEN, INNER);
}